// round 3
// baseline (speedup 1.0000x reference)
#include <cuda_runtime.h>
#include <math.h>

#define N_NODES 65536
#define DIM     128
#define GR      128
#define LN      512
#define NE      262144
#define GSTEPS  6

// ---------------- scratch (static device allocations; no cudaMalloc) ----------------
__device__ float g_H  [N_NODES * DIM];        // node state h
__device__ float g_M  [N_NODES * DIM];        // messages m = h @ w
__device__ float g_AGG[N_NODES * DIM];        // scatter-add result
__device__ float g_GX [N_NODES * 384];        // agg @ wih^T + bih
__device__ float g_GH [N_NODES * 384];        // h   @ whh^T + bhh
__device__ float g_WT [GSTEPS * DIM * DIM];   // transposed ggnn weights
__device__ float g_CAT[256 * N_NODES];        // [256][G*512]: ch 0..127 = h, 128..255 = x
__device__ float g_T1 [128 * GR * 510];
__device__ float g_P1 [128 * GR * 254];
__device__ float g_T2 [128 * GR * 254];
__device__ float g_P2 [128 * GR * 127];
__device__ float g_U1 [256 * GR * 510];
__device__ float g_Q1 [256 * GR * 254];
__device__ float g_U2 [256 * GR * 254];
__device__ float g_Q2 [256 * GR * 127];
__device__ float g_MEAN[256];
__device__ float g_RSTD[256];

// ---------------- 128x128x8 fp32 SGEMM:  C[M,N] = A[M,K] * B[N,K]^T (+bias per col) ----------------
__global__ __launch_bounds__(256) void gemm_nt(
    const float* __restrict__ A, const float* __restrict__ B,
    const float* __restrict__ bias, float* __restrict__ C,
    int Ncols, int K)
{
    __shared__ float As[2][8][128];
    __shared__ float Bs[2][8][128];
    const int tid  = threadIdx.x;
    const int lrow = tid >> 1;
    const int lcol = (tid & 1) << 2;
    const int tx   = tid & 15;
    const int ty   = tid >> 4;

    const float* Ab = A + (size_t)blockIdx.x * 128 * K + (size_t)lrow * K + lcol;
    const float* Bb = B + (size_t)blockIdx.y * 128 * K + (size_t)lrow * K + lcol;

    float acc[8][8];
#pragma unroll
    for (int i = 0; i < 8; i++)
#pragma unroll
        for (int j = 0; j < 8; j++) acc[i][j] = 0.f;

    {
        float4 av = *(const float4*)Ab;
        float4 bv = *(const float4*)Bb;
        As[0][lcol + 0][lrow] = av.x; As[0][lcol + 1][lrow] = av.y;
        As[0][lcol + 2][lrow] = av.z; As[0][lcol + 3][lrow] = av.w;
        Bs[0][lcol + 0][lrow] = bv.x; Bs[0][lcol + 1][lrow] = bv.y;
        Bs[0][lcol + 2][lrow] = bv.z; Bs[0][lcol + 3][lrow] = bv.w;
    }
    __syncthreads();

    const int nk = K >> 3;
    int buf = 0;
    for (int kt = 0; kt < nk; kt++) {
        float4 avn, bvn;
        const bool has = (kt + 1) < nk;
        if (has) {
            avn = *(const float4*)(Ab + (kt + 1) * 8);
            bvn = *(const float4*)(Bb + (kt + 1) * 8);
        }
        const float (*Ap)[128] = As[buf];
        const float (*Bp)[128] = Bs[buf];
#pragma unroll
        for (int kk = 0; kk < 8; kk++) {
            float a[8], b[8];
#pragma unroll
            for (int i = 0; i < 8; i++) a[i] = Ap[kk][ty * 8 + i];
#pragma unroll
            for (int j = 0; j < 8; j++) b[j] = Bp[kk][tx * 8 + j];
#pragma unroll
            for (int i = 0; i < 8; i++)
#pragma unroll
                for (int j = 0; j < 8; j++) acc[i][j] = fmaf(a[i], b[j], acc[i][j]);
        }
        if (has) {
            const int nb = buf ^ 1;
            As[nb][lcol + 0][lrow] = avn.x; As[nb][lcol + 1][lrow] = avn.y;
            As[nb][lcol + 2][lrow] = avn.z; As[nb][lcol + 3][lrow] = avn.w;
            Bs[nb][lcol + 0][lrow] = bvn.x; Bs[nb][lcol + 1][lrow] = bvn.y;
            Bs[nb][lcol + 2][lrow] = bvn.z; Bs[nb][lcol + 3][lrow] = bvn.w;
        }
        __syncthreads();
        buf ^= 1;
    }

    const int col0 = blockIdx.y * 128 + tx * 8;
    const int row0 = blockIdx.x * 128 + ty * 8;
    float badd[8];
#pragma unroll
    for (int j = 0; j < 8; j++) badd[j] = bias ? bias[col0 + j] : 0.f;
#pragma unroll
    for (int i = 0; i < 8; i++) {
        float4 v0 = make_float4(acc[i][0] + badd[0], acc[i][1] + badd[1],
                                acc[i][2] + badd[2], acc[i][3] + badd[3]);
        float4 v1 = make_float4(acc[i][4] + badd[4], acc[i][5] + badd[5],
                                acc[i][6] + badd[6], acc[i][7] + badd[7]);
        *(float4*)(C + (size_t)(row0 + i) * Ncols + col0)     = v0;
        *(float4*)(C + (size_t)(row0 + i) * Ncols + col0 + 4) = v1;
    }
}

// ---------------- conv1d as implicit-im2col GEMM ----------------
// C[co][n] = sum_{ci,t} W[co][ci*KW+t] * X[ci][g(n)*Lin + l(n) + t]  (+bias per row)
// X channel-major [Cch][G][Lin], C channel-major [Cout][G][Lout], n = g*Lout + l
template<int KW>
__global__ __launch_bounds__(256) void conv_gemm(
    const float* __restrict__ W, const float* __restrict__ X,
    const float* __restrict__ bias, float* __restrict__ C,
    int Kp, int Ncols, int Lin, int Lout, int GLin)
{
    __shared__ float As[2][8][128];
    __shared__ float Bs[2][8][128];
    const int tid  = threadIdx.x;
    const int lrow = tid >> 1;
    const int lcol = (tid & 1) << 2;
    const int tx   = tid & 15;
    const int ty   = tid >> 4;

    const float* Ab = W + (size_t)blockIdx.y * 128 * Kp + (size_t)lrow * Kp + lcol;

    const int bn_l  = tid & 127;
    const int kb    = (tid >> 7) << 2;
    const int nglob = blockIdx.x * 128 + bn_l;
    const int g     = nglob / Lout;
    const int l     = nglob - g * Lout;
    const float* Xb = X + (size_t)g * Lin + l;

    float acc[8][8];
#pragma unroll
    for (int i = 0; i < 8; i++)
#pragma unroll
        for (int j = 0; j < 8; j++) acc[i][j] = 0.f;

    {
        float4 av = *(const float4*)Ab;
        As[0][lcol + 0][lrow] = av.x; As[0][lcol + 1][lrow] = av.y;
        As[0][lcol + 2][lrow] = av.z; As[0][lcol + 3][lrow] = av.w;
#pragma unroll
        for (int i = 0; i < 4; i++) {
            const int kp = kb + i;
            const int ci = kp / KW;
            const int t  = kp - ci * KW;
            Bs[0][kb + i][bn_l] = Xb[(size_t)ci * GLin + t];
        }
    }
    __syncthreads();

    const int nk = Kp >> 3;
    int buf = 0;
    for (int kt = 0; kt < nk; kt++) {
        float4 avn;
        float  bvn[4];
        const bool has = (kt + 1) < nk;
        if (has) {
            avn = *(const float4*)(Ab + (kt + 1) * 8);
            const int k0 = (kt + 1) * 8;
#pragma unroll
            for (int i = 0; i < 4; i++) {
                const int kp = k0 + kb + i;
                const int ci = kp / KW;
                const int t  = kp - ci * KW;
                bvn[i] = Xb[(size_t)ci * GLin + t];
            }
        }
        const float (*Ap)[128] = As[buf];
        const float (*Bp)[128] = Bs[buf];
#pragma unroll
        for (int kk = 0; kk < 8; kk++) {
            float a[8], b[8];
#pragma unroll
            for (int i = 0; i < 8; i++) a[i] = Ap[kk][ty * 8 + i];
#pragma unroll
            for (int j = 0; j < 8; j++) b[j] = Bp[kk][tx * 8 + j];
#pragma unroll
            for (int i = 0; i < 8; i++)
#pragma unroll
                for (int j = 0; j < 8; j++) acc[i][j] = fmaf(a[i], b[j], acc[i][j]);
        }
        if (has) {
            const int nb = buf ^ 1;
            As[nb][lcol + 0][lrow] = avn.x; As[nb][lcol + 1][lrow] = avn.y;
            As[nb][lcol + 2][lrow] = avn.z; As[nb][lcol + 3][lrow] = avn.w;
#pragma unroll
            for (int i = 0; i < 4; i++) Bs[nb][kb + i][bn_l] = bvn[i];
        }
        __syncthreads();
        buf ^= 1;
    }

    const int row0 = blockIdx.y * 128 + ty * 8;
    const int col0 = blockIdx.x * 128 + tx * 8;
#pragma unroll
    for (int i = 0; i < 8; i++) {
        const float bo = bias[row0 + i];
        float4 v0 = make_float4(acc[i][0] + bo, acc[i][1] + bo, acc[i][2] + bo, acc[i][3] + bo);
        float4 v1 = make_float4(acc[i][4] + bo, acc[i][5] + bo, acc[i][6] + bo, acc[i][7] + bo);
        *(float4*)(C + (size_t)(row0 + i) * Ncols + col0)     = v0;
        *(float4*)(C + (size_t)(row0 + i) * Ncols + col0 + 4) = v1;
    }
}

// ---------------- edge scatter: agg[dst] += ew * m[src] ----------------
__global__ void scatter_kernel(const float* __restrict__ Msg, const int* __restrict__ ei,
                               const float* __restrict__ ew, float* __restrict__ AGG)
{
    const int t = blockIdx.x * blockDim.x + threadIdx.x;
    const int e = t >> 5;
    const int j = (t & 31) << 2;
    const int s = ei[e];
    const int d = ei[NE + e];
    const float w = ew[e];
    const float4 v = *(const float4*)(Msg + (size_t)s * DIM + j);
    float* b = AGG + (size_t)d * DIM + j;
    atomicAdd(b + 0, v.x * w);
    atomicAdd(b + 1, v.y * w);
    atomicAdd(b + 2, v.z * w);
    atomicAdd(b + 3, v.w * w);
}

// ---------------- GRU elementwise update (in-place on H) ----------------
__global__ void gru_kernel(const float* __restrict__ GX, const float* __restrict__ GH,
                           float* __restrict__ H)
{
    const size_t t = (size_t)blockIdx.x * blockDim.x + threadIdx.x;
    const size_t i = t >> 7;
    const int    j = (int)(t & 127);
    const float* px = GX + i * 384;
    const float* ph = GH + i * 384;
    const float xr = px[j], xz = px[128 + j], xn = px[256 + j];
    const float hr = ph[j], hz = ph[128 + j], hn = ph[256 + j];
    const float r = 1.f / (1.f + expf(-(xr + hr)));
    const float z = 1.f / (1.f + expf(-(xz + hz)));
    const float n = tanhf(xn + r * hn);
    float* hp = H + i * 128 + j;
    *hp = (1.f - z) * n + z * (*hp);
}

// ---------------- [N,128] -> [128,N] transpose into CAT ----------------
__global__ void transpose_nd(const float* __restrict__ src, float* __restrict__ dst)
{
    __shared__ float tile[32][33];
    const int nb = blockIdx.x << 5;
    const int cb = blockIdx.y << 5;
    const int tx = threadIdx.x, ty = threadIdx.y;
#pragma unroll
    for (int i = 0; i < 32; i += 8)
        tile[ty + i][tx] = src[(size_t)(nb + ty + i) * DIM + cb + tx];
    __syncthreads();
#pragma unroll
    for (int i = 0; i < 32; i += 8)
        dst[(size_t)(cb + ty + i) * N_NODES + nb + tx] = tile[tx][ty + i];
}

// ---------------- transpose the 6 ggnn weight matrices: wT[s][j][k] = w[s][k][j] ----------------
__global__ void transpose_w_kernel(const float* __restrict__ w, float* __restrict__ wT)
{
    const int t = blockIdx.x * 256 + threadIdx.x;   // 6*16384 total
    const int s = t >> 14;
    const int j = (t >> 7) & 127;
    const int k = t & 127;
    wT[t] = w[(s << 14) + (k << 7) + j];
}

// ---------------- per-channel mean / rstd over [G*Lout] (training-mode BN stats) ----------------
__global__ void bnstats_kernel(const float* __restrict__ T, int len,
                               float* __restrict__ mean, float* __restrict__ rstd)
{
    __shared__ double sh[256], sh2[256];
    const int c = blockIdx.x;
    const float* p = T + (size_t)c * len;
    double s = 0.0, s2 = 0.0;
    for (int i = threadIdx.x; i < len; i += 256) {
        const double v = (double)p[i];
        s += v; s2 += v * v;
    }
    sh[threadIdx.x] = s; sh2[threadIdx.x] = s2;
    __syncthreads();
    for (int st = 128; st > 0; st >>= 1) {
        if (threadIdx.x < st) {
            sh[threadIdx.x]  += sh[threadIdx.x + st];
            sh2[threadIdx.x] += sh2[threadIdx.x + st];
        }
        __syncthreads();
    }
    if (threadIdx.x == 0) {
        const double m   = sh[0] / len;
        const double var = sh2[0] / len - m * m;
        mean[c] = (float)m;
        rstd[c] = (float)(1.0 / sqrt(var + 1e-5));
    }
}

// ---------------- fused BN(affine) + ReLU + MaxPool ----------------
template<int PK, int PS>
__global__ void bn_relu_pool(const float* __restrict__ T, const float* __restrict__ mean,
                             const float* __restrict__ rstd, const float* __restrict__ gamma,
                             const float* __restrict__ beta, float* __restrict__ O,
                             int Lin, int Lpool, int total)
{
    const int idx = blockIdx.x * 256 + threadIdx.x;
    if (idx >= total) return;
    const int lp   = idx % Lpool;
    const int rest = idx / Lpool;
    const int g    = rest & 127;
    const int c    = rest >> 7;
    const float* p = T + ((size_t)c * GR + g) * Lin + lp * PS;
    const float a = rstd[c] * gamma[c];
    const float b = beta[c] - mean[c] * a;
    float mx = 0.f;   // ReLU floor
#pragma unroll
    for (int t = 0; t < PK; t++) mx = fmaxf(mx, fmaf(p[t], a, b));
    O[idx] = mx;
}

// ---------------- readout: (Y2 @ wy^T + by) * (Z2 @ wz^T + bz), mean over L'=127 ----------------
__global__ void final_kernel(const float* __restrict__ P2, const float* __restrict__ Q2,
                             const float* __restrict__ wy, const float* __restrict__ by,
                             const float* __restrict__ wz, const float* __restrict__ bz,
                             float* __restrict__ out)
{
    const int g = blockIdx.x;
    __shared__ float s0[128], s1[128];
    const int l = threadIdx.x;
    float a0 = 0.f, a1 = 0.f;
    if (l < 127) {
        float y0 = by[0], y1 = by[1];
#pragma unroll 4
        for (int d = 0; d < 128; d++) {
            const float v = P2[((size_t)d * GR + g) * 127 + l];
            y0 = fmaf(v, wy[d],        y0);
            y1 = fmaf(v, wy[128 + d],  y1);
        }
        float z0 = bz[0], z1 = bz[1];
#pragma unroll 4
        for (int cc = 0; cc < 256; cc++) {
            const float v = Q2[((size_t)cc * GR + g) * 127 + l];
            z0 = fmaf(v, wz[cc],       z0);
            z1 = fmaf(v, wz[256 + cc], z1);
        }
        a0 = y0 * z0; a1 = y1 * z1;
    }
    s0[l] = a0; s1[l] = a1;
    __syncthreads();
    for (int st = 64; st > 0; st >>= 1) {
        if (l < st) { s0[l] += s0[l + st]; s1[l] += s1[l + st]; }
        __syncthreads();
    }
    if (l == 0) {
        out[g * 2 + 0] = s0[0] / 127.f;
        out[g * 2 + 1] = s1[0] / 127.f;
    }
}

// ---------------- host orchestration (graph-capturable: kernels + async memops only) ----------------
extern "C" void kernel_launch(void* const* d_in, const int* in_sizes, int n_in,
                              void* d_out, int out_size)
{
    const float* x    = (const float*)d_in[0];
    const int*   ei   = (const int*)  d_in[1];
    const float* ew   = (const float*)d_in[2];
    // d_in[3] = batch (structure is a pure reshape; unused)
    const float* ggw  = (const float*)d_in[4];
    const float* wih  = (const float*)d_in[5];
    const float* whh  = (const float*)d_in[6];
    const float* bih  = (const float*)d_in[7];
    const float* bhh  = (const float*)d_in[8];
    const float* c1w  = (const float*)d_in[9];
    const float* c1b  = (const float*)d_in[10];
    const float* c2w  = (const float*)d_in[11];
    const float* c2b  = (const float*)d_in[12];
    const float* cc1w = (const float*)d_in[13];
    const float* cc1b = (const float*)d_in[14];
    const float* cc2w = (const float*)d_in[15];
    const float* cc2b = (const float*)d_in[16];
    const float* bn1g = (const float*)d_in[17];
    const float* bn1b = (const float*)d_in[18];
    const float* bn2g = (const float*)d_in[19];
    const float* bn2b = (const float*)d_in[20];
    const float* myw  = (const float*)d_in[21];
    const float* myb  = (const float*)d_in[22];
    const float* mzw  = (const float*)d_in[23];
    const float* mzb  = (const float*)d_in[24];
    float* out = (float*)d_out;

    float *H, *Msg, *AGG, *GX, *GH, *WT, *CAT, *T1, *P1, *T2, *P2, *U1, *Q1, *U2, *Q2, *MEAN, *RSTD;
    cudaGetSymbolAddress((void**)&H,   g_H);
    cudaGetSymbolAddress((void**)&Msg, g_M);
    cudaGetSymbolAddress((void**)&AGG, g_AGG);
    cudaGetSymbolAddress((void**)&GX,  g_GX);
    cudaGetSymbolAddress((void**)&GH,  g_GH);
    cudaGetSymbolAddress((void**)&WT,  g_WT);
    cudaGetSymbolAddress((void**)&CAT, g_CAT);
    cudaGetSymbolAddress((void**)&T1,  g_T1);
    cudaGetSymbolAddress((void**)&P1,  g_P1);
    cudaGetSymbolAddress((void**)&T2,  g_T2);
    cudaGetSymbolAddress((void**)&P2,  g_P2);
    cudaGetSymbolAddress((void**)&U1,  g_U1);
    cudaGetSymbolAddress((void**)&Q1,  g_Q1);
    cudaGetSymbolAddress((void**)&U2,  g_U2);
    cudaGetSymbolAddress((void**)&Q2,  g_Q2);
    cudaGetSymbolAddress((void**)&MEAN, g_MEAN);
    cudaGetSymbolAddress((void**)&RSTD, g_RSTD);

    const size_t ndbytes = (size_t)N_NODES * DIM * sizeof(float);

    // h0 = x
    cudaMemcpyAsync(H, x, ndbytes, cudaMemcpyDeviceToDevice);
    transpose_w_kernel<<<(GSTEPS * DIM * DIM) / 256, 256>>>(ggw, WT);

    for (int s = 0; s < GSTEPS; s++) {
        // m = h @ w[s]
        gemm_nt<<<dim3(512, 1), 256>>>(H, WT + s * DIM * DIM, nullptr, Msg, 128, 128);
        // agg = scatter_add(ew * m[src] -> dst)
        cudaMemsetAsync(AGG, 0, ndbytes);
        scatter_kernel<<<(NE * 32) / 256, 256>>>(Msg, ei, ew, AGG);
        // gx = agg @ wih^T + bih ; gh = h @ whh^T + bhh
        gemm_nt<<<dim3(512, 3), 256>>>(AGG, wih, bih, GX, 384, 128);
        gemm_nt<<<dim3(512, 3), 256>>>(H,   whh, bhh, GH, 384, 128);
        // h = GRU(agg, h)
        gru_kernel<<<(N_NODES * DIM) / 256, 256>>>(GX, GH, H);
    }

    // CAT = [h^T ; x^T] channel-major [256][G*512]
    transpose_nd<<<dim3(N_NODES / 32, 4), dim3(32, 8)>>>(H, CAT);
    transpose_nd<<<dim3(N_NODES / 32, 4), dim3(32, 8)>>>(x, CAT + (size_t)128 * N_NODES);

    // ---- branch Y (h only, 128 ch) ----
    conv_gemm<3><<<dim3(510, 1), 256>>>(c1w, CAT, c1b, T1, 384, 65280, 512, 510, 65536);
    bnstats_kernel<<<128, 256>>>(T1, 65280, MEAN, RSTD);
    bn_relu_pool<3, 2><<<(128 * GR * 254) / 256, 256>>>(T1, MEAN, RSTD, bn1g, bn1b, P1, 510, 254, 128 * GR * 254);
    conv_gemm<1><<<dim3(254, 1), 256>>>(c2w, P1, c2b, T2, 128, 32512, 254, 254, 32512);
    bnstats_kernel<<<128, 256>>>(T2, 32512, MEAN, RSTD);
    bn_relu_pool<2, 2><<<(128 * GR * 127) / 256, 256>>>(T2, MEAN, RSTD, bn1g, bn1b, P2, 254, 127, 128 * GR * 127);

    // ---- branch Z (concat [h;x], 256 ch) ----
    conv_gemm<3><<<dim3(510, 2), 256>>>(cc1w, CAT, cc1b, U1, 768, 65280, 512, 510, 65536);
    bnstats_kernel<<<256, 256>>>(U1, 65280, MEAN, RSTD);
    bn_relu_pool<3, 2><<<(256 * GR * 254) / 256, 256>>>(U1, MEAN, RSTD, bn2g, bn2b, Q1, 510, 254, 256 * GR * 254);
    conv_gemm<1><<<dim3(254, 2), 256>>>(cc2w, Q1, cc2b, U2, 256, 32512, 254, 254, 32512);
    bnstats_kernel<<<256, 256>>>(U2, 32512, MEAN, RSTD);
    bn_relu_pool<2, 2><<<(256 * GR * 127) / 256, 256>>>(U2, MEAN, RSTD, bn2g, bn2b, Q2, 254, 127, 256 * GR * 127);

    // ---- readout ----
    final_kernel<<<GR, 128>>>(P2, Q2, myw, myb, mzw, mzb, out);
}